// round 14
// baseline (speedup 1.0000x reference)
#include <cuda_runtime.h>
#include <cuda_fp16.h>
#include <cstdint>

// ---------------------------------------------------------------------------
// TeamMovementModel R14: R13 lstm (fused gate-ownership HMMA, fp32 acc,
// 1 barrier/step, x-prefetch, unroll-2 ping-pong) + fc FUSED into the kernel
// tail. Player CTAs keep their 16 seqs' final h fp32 in smem (aliasing the
// dead x buffer); ball CTAs publish ball_h via g_hid + fence + counter;
// player CTAs epoch-spin on the counter (all 92 CTAs co-resident -> safe),
// then compute their 16x40 fc outputs from smem. No second kernel.
//   92 CTAs x 16 seqs, 512 threads, K=128 fp16, fp32 c-state.
// ---------------------------------------------------------------------------

#define Hh        128
#define GATES     512
#define Tt        128
#define SEQS      16
#define NCTAS     92
#define PCTAS     88
#define NBALLCTA  4
#define NPLAYER   1408
#define NBALL     64
#define THREADS   512
#define NKT       8             // K tiles of 16 (K=128)
#define BS        136           // h tile row stride in halves (conflict-free)
#define HBS       132           // hbuf row stride in floats (conflict-free)

// dynamic smem layout (bytes)
#define OFF_XS    0                         // x stage [128 t][16 s] float2; tail: hbuf [16][132] f32
#define SZ_XS     (Tt * SEQS * 8)           // 16384
#define OFF_B0    (OFF_XS + SZ_XS)          // 16384
#define SZ_B      (SEQS * BS * 2)           // 4352
#define OFF_B1    (OFF_B0 + SZ_B)           // 20736
#define OFF_FW    (OFF_B1 + SZ_B)           // 25088
#define SZ_FW     (40 * 258 * 4)            // 41280
#define OFF_BB    (OFF_FW + SZ_FW)          // 66368
#define SZ_BB     (2 * 128 * 4)             // 1024
#define SM_BYTES  (OFF_BB + SZ_BB)          // 67392

__device__ float g_hid[NBALL * Hh];                   // ball hidden states only
__device__ unsigned long long ball_ctr   = 0;         // monotonic across replays
__device__ unsigned long long player_ctr = 0;

__device__ __forceinline__ float tanhap(float x) {
    float y; asm("tanh.approx.f32 %0, %1;" : "=f"(y) : "f"(x)); return y;
}
__device__ __forceinline__ float sigap(float x) {
    return fmaf(0.5f, tanhap(0.5f * x), 0.5f);
}
__device__ __forceinline__ uint32_t h2pack(float a, float b) {
    __half2 h = __halves2half2(__float2half(a), __float2half(b));
    return *reinterpret_cast<uint32_t*>(&h);
}

// m16n8k16 row.col f32.f16.f16.f32, accumulate in place.
__device__ __forceinline__ void mma16816(float* d, const uint32_t* a,
                                         uint32_t b0, uint32_t b1) {
    asm volatile(
        "mma.sync.aligned.m16n8k16.row.col.f32.f16.f16.f32 "
        "{%0,%1,%2,%3}, {%4,%5,%6,%7}, {%8,%9}, {%0,%1,%2,%3};"
        : "+f"(d[0]), "+f"(d[1]), "+f"(d[2]), "+f"(d[3])
        : "r"(a[0]), "r"(a[1]), "r"(a[2]), "r"(a[3]), "r"(b0), "r"(b1));
}

struct StepState {
    uint32_t (*Af)[NKT][4];
    const float* wx0; const float* wx1; const float* bsr;
    float* c;
    int r0, c0, u;
};

// One LSTM step: reads h from Bcur, writes h(t+1) fp16 to Bnxt; on the last
// step also stores h fp32 into hbuf (smem, conflict-free stride 132).
__device__ __forceinline__ void lstm_step(
    const StepState& S, const __half* Bcur, __half* Bnxt,
    const float2* xf, bool last, float* hbuf)
{
    float D[2][2][4];
    #pragma unroll
    for (int nt = 0; nt < 2; nt++) {
        #pragma unroll
        for (int e1 = 0; e1 < 2; e1++) {
            const float2 x = xf[nt * 2 + e1];
            D[0][nt][e1]     = fmaf(S.wx1[0], x.y, fmaf(S.wx0[0], x.x, S.bsr[0]));
            D[0][nt][2 + e1] = fmaf(S.wx1[1], x.y, fmaf(S.wx0[1], x.x, S.bsr[1]));
            D[1][nt][e1]     = fmaf(S.wx1[2], x.y, fmaf(S.wx0[2], x.x, S.bsr[2]));
            D[1][nt][2 + e1] = fmaf(S.wx1[3], x.y, fmaf(S.wx0[3], x.x, S.bsr[3]));
        }
    }

    #pragma unroll
    for (int kt = 0; kt < NKT; kt++) {
        const int kh = kt * 16 + S.c0;
        const __half* bp0 = Bcur + S.r0 * BS + kh;
        const __half* bp1 = bp0 + 8 * BS;
        const uint32_t b00 = *reinterpret_cast<const uint32_t*>(bp0);
        const uint32_t b01 = *reinterpret_cast<const uint32_t*>(bp0 + 8);
        const uint32_t b10 = *reinterpret_cast<const uint32_t*>(bp1);
        const uint32_t b11 = *reinterpret_cast<const uint32_t*>(bp1 + 8);
        mma16816(D[0][0], S.Af[0][kt], b00, b01);
        mma16816(D[0][1], S.Af[0][kt], b10, b11);
        mma16816(D[1][0], S.Af[1][kt], b00, b01);
        mma16816(D[1][1], S.Af[1][kt], b10, b11);
    }

    #pragma unroll
    for (int j = 0; j < 4; j++) {
        const int nt = j >> 1, e1 = j & 1;
        const int m  = nt * 8 + S.c0 + e1;
        const float gi = sigap(D[0][nt][e1]);
        const float gf = sigap(D[0][nt][2 + e1]);
        const float gg = tanhap(D[1][nt][e1]);
        const float go = sigap(D[1][nt][2 + e1]);
        S.c[j] = gf * S.c[j] + gi * gg;
        const float h = go * tanhap(S.c[j]);
        Bnxt[m * BS + S.u] = __float2half(h);
        if (last)
            hbuf[m * HBS + S.u] = h;
    }
}

__global__ __launch_bounds__(THREADS, 1)
void lstm_fused_kernel(const float* __restrict__ xp, const float* __restrict__ xb,
                       const float* __restrict__ p_wih, const float* __restrict__ p_whh,
                       const float* __restrict__ p_bih, const float* __restrict__ p_bhh,
                       const float* __restrict__ b_wih, const float* __restrict__ b_whh,
                       const float* __restrict__ b_bih, const float* __restrict__ b_bhh,
                       const float* __restrict__ fc_w, const float* __restrict__ fc_b,
                       float* __restrict__ out)
{
    extern __shared__ unsigned char dsm[];
    float2* xs   = reinterpret_cast<float2*>(dsm + OFF_XS);   // x stage
    float*  hbuf = reinterpret_cast<float*>(dsm + OFF_XS);    // aliases xs (tail)
    __half* B0   = reinterpret_cast<__half*>(dsm + OFF_B0);
    __half* B1   = reinterpret_cast<__half*>(dsm + OFF_B1);
    float*  fw   = reinterpret_cast<float*>(dsm + OFF_FW);
    float*  bbs  = reinterpret_cast<float*>(dsm + OFF_BB);

    const int tid = threadIdx.x;
    const int w   = tid >> 5;
    const int ln  = tid & 31;
    const int cta = blockIdx.x;
    const bool is_ball = (cta >= PCTAS);

    const float* wih_ = is_ball ? b_wih : p_wih;
    const float* whh_ = is_ball ? b_whh : p_whh;
    const float* bih_ = is_ball ? b_bih : p_bih;
    const float* bhh_ = is_ball ? b_bhh : p_bhh;
    const float* xsrc = is_ball ? xb : xp;
    const int s0 = is_ball ? (cta - PCTAS) * SEQS : cta * SEQS;

    // ---- zero both h buffers, stage x ----
    for (int i = tid; i < SEQS * BS / 2; i += THREADS) {
        reinterpret_cast<uint32_t*>(B0)[i] = 0;
        reinterpret_cast<uint32_t*>(B1)[i] = 0;
    }
    for (int i = tid; i < Tt * SEQS; i += THREADS) {
        int s = i >> 7, t = i & 127;
        xs[t * SEQS + s] = *reinterpret_cast<const float2*>(
            xsrc + (size_t)(s0 + s) * 256 + t * 2);
    }

    const int r0 = ln >> 2;
    const int c0 = (ln & 3) * 2;
    const int u  = w * 8 + r0;

    // ---- A fragments: mt0 rows = {i(u), f(u)}, mt1 rows = {g(u), o(u)} ----
    uint32_t Af[2][NKT][4];
    #pragma unroll
    for (int mt = 0; mt < 2; mt++) {
        const float* wrA = whh_ + (size_t)((mt * 2 + 0) * Hh + u) * Hh;
        const float* wrB = whh_ + (size_t)((mt * 2 + 1) * Hh + u) * Hh;
        #pragma unroll
        for (int kt = 0; kt < NKT; kt++) {
            const int k = kt * 16 + c0;
            float2 aA0 = *reinterpret_cast<const float2*>(wrA + k);
            float2 aB0 = *reinterpret_cast<const float2*>(wrB + k);
            float2 aA1 = *reinterpret_cast<const float2*>(wrA + k + 8);
            float2 aB1 = *reinterpret_cast<const float2*>(wrB + k + 8);
            Af[mt][kt][0] = h2pack(aA0.x, aA0.y);
            Af[mt][kt][1] = h2pack(aB0.x, aB0.y);
            Af[mt][kt][2] = h2pack(aA1.x, aA1.y);
            Af[mt][kt][3] = h2pack(aB1.x, aB1.y);
        }
    }

    float wx0[4], wx1[4], bsr[4];
    #pragma unroll
    for (int q = 0; q < 4; q++) {
        const int g = q * Hh + u;
        wx0[q] = wih_[g * 2 + 0];
        wx1[q] = wih_[g * 2 + 1];
        bsr[q] = bih_[g] + bhh_[g];
    }

    float c[4] = {0.f, 0.f, 0.f, 0.f};

    StepState S;
    S.Af = Af; S.wx0 = wx0; S.wx1 = wx1; S.bsr = bsr; S.c = c;
    S.r0 = r0; S.c0 = c0; S.u = u;

    __syncthreads();

    float2 xf[4];
    xf[0] = xs[0 * SEQS + c0];     xf[1] = xs[0 * SEQS + c0 + 1];
    xf[2] = xs[0 * SEQS + 8 + c0]; xf[3] = xs[0 * SEQS + 8 + c0 + 1];

    #pragma unroll 1
    for (int t = 0; t < Tt; t += 2) {
        lstm_step(S, B0, B1, xf, false, hbuf);
        {
            const int tn = t + 1;
            xf[0] = xs[tn * SEQS + c0];     xf[1] = xs[tn * SEQS + c0 + 1];
            xf[2] = xs[tn * SEQS + 8 + c0]; xf[3] = xs[tn * SEQS + 8 + c0 + 1];
        }
        __syncthreads();
        lstm_step(S, B1, B0, xf, t + 1 == Tt - 1, hbuf);
        if (t + 2 < Tt) {
            const int tn = t + 2;
            xf[0] = xs[tn * SEQS + c0];     xf[1] = xs[tn * SEQS + c0 + 1];
            xf[2] = xs[tn * SEQS + 8 + c0]; xf[3] = xs[tn * SEQS + 8 + c0 + 1];
        }
        __syncthreads();
    }
    // hbuf now holds this CTA's final h [16][HBS] fp32.

    if (is_ball) {
        // publish ball h, then release-signal
        for (int i = tid; i < SEQS * Hh; i += THREADS) {
            const int m = i >> 7, k = i & 127;
            g_hid[(size_t)(s0 + m) * Hh + k] = hbuf[m * HBS + k];
        }
        __threadfence();
        __syncthreads();
        if (tid == 0) atomicAdd(&ball_ctr, 1ULL);
        return;
    }

    // ---- player tail: fc for own 16 seqs ----
    // load fc weights into smem (overlaps ball publication)
    for (int i = tid; i < 40 * 256; i += THREADS) {
        const int j = i >> 8, k = i & 255;
        fw[j * 258 + k] = fc_w[i];
    }
    // epoch spin: wait for this replay's 4 ball CTAs
    if (tid == 0) {
        const unsigned long long ticket = atomicAdd(&player_ctr, 1ULL);
        const unsigned long long target = (ticket / (unsigned long long)PCTAS + 1ULL)
                                          * (unsigned long long)NBALLCTA;
        while (*(volatile unsigned long long*)&ball_ctr < target)
            __nanosleep(64);
        __threadfence();
    }
    __syncthreads();

    // stage the (at most 2) ball rows this CTA needs
    const int bfirst = s0 / 22;
    const int blast  = (s0 + SEQS - 1) / 22;
    for (int i = tid; i < 256; i += THREADS) {
        const int which = i >> 7, k = i & 127;
        const int bsel  = which ? blast : bfirst;
        bbs[i] = g_hid[(size_t)bsel * Hh + k];
    }
    __syncthreads();

    // 640 outputs: o = s_local*40 + j
    for (int o = tid; o < SEQS * 40; o += THREADS) {
        const int sl = o / 40;
        const int j  = o - sl * 40;
        const int b  = (s0 + sl) / 22;
        const float* ph = hbuf + sl * HBS;
        const float* bl = bbs + ((b == bfirst) ? 0 : 128);
        const float* fr = fw + j * 258;
        float acc = fc_b[j];
        #pragma unroll 16
        for (int k = 0; k < 128; k++) acc = fmaf(ph[k], fr[k], acc);
        #pragma unroll 16
        for (int k = 0; k < 128; k++) acc = fmaf(bl[k], fr[128 + k], acc);
        out[(size_t)(s0 + sl) * 40 + j] = acc;
    }
}

extern "C" void kernel_launch(void* const* d_in, const int* in_sizes, int n_in,
                              void* d_out, int out_size)
{
    const float* xp    = (const float*)d_in[0];
    const float* xb    = (const float*)d_in[1];
    const float* p_wih = (const float*)d_in[2];
    const float* p_whh = (const float*)d_in[3];
    const float* p_bih = (const float*)d_in[4];
    const float* p_bhh = (const float*)d_in[5];
    const float* b_wih = (const float*)d_in[6];
    const float* b_whh = (const float*)d_in[7];
    const float* b_bih = (const float*)d_in[8];
    const float* b_bhh = (const float*)d_in[9];
    const float* fc_w  = (const float*)d_in[10];
    const float* fc_b  = (const float*)d_in[11];
    float* out = (float*)d_out;

    cudaFuncSetAttribute(lstm_fused_kernel,
                         cudaFuncAttributeMaxDynamicSharedMemorySize, SM_BYTES);

    lstm_fused_kernel<<<NCTAS, THREADS, SM_BYTES>>>(
        xp, xb, p_wih, p_whh, p_bih, p_bhh,
        b_wih, b_whh, b_bih, b_bhh, fc_w, fc_b, out);
}

// round 15
// speedup vs baseline: 1.1922x; 1.1922x over previous
#include <cuda_runtime.h>
#include <cuda_fp16.h>
#include <cstdint>

// ---------------------------------------------------------------------------
// TeamMovementModel R15: two-group software-pipelined HMMA LSTM.
// ncu (R14) showed tensor=42%/issue=53% on busy SMs -> step is stall-bound,
// not pipe-bound. Split the 16 seqs into two n8 groups (A, B) and pipeline:
//   [mmaA(t) || epiB(t-1)]  bar  [mmaB(t) || epiA(t)]  bar
// MMA chains of one group overlap the MUFU epilogue of the other.
// Single-buffered per-group h tiles (bar-separated read/write phases).
// fc back to the separate smem kernel (R14 fusion measured -4 us worse).
//   92 CTAs x 16 seqs, 512 threads, K=128 fp16, fp32 c-state.
// ---------------------------------------------------------------------------

#define Hh        128
#define GATES     512
#define Tt        128
#define SEQS      16
#define NCTAS     92
#define PCTAS     88
#define NPLAYER   1408
#define NBALL     64
#define THREADS   512
#define NKT       8             // K tiles of 16 (K=128)
#define BS        136           // h tile row stride in halves (conflict-free)

__device__ float g_hid[(NPLAYER + NBALL) * Hh];

__device__ __forceinline__ float tanhap(float x) {
    float y; asm("tanh.approx.f32 %0, %1;" : "=f"(y) : "f"(x)); return y;
}
__device__ __forceinline__ float sigap(float x) {
    return fmaf(0.5f, tanhap(0.5f * x), 0.5f);
}
__device__ __forceinline__ uint32_t h2pack(float a, float b) {
    __half2 h = __halves2half2(__float2half(a), __float2half(b));
    return *reinterpret_cast<uint32_t*>(&h);
}

// m16n8k16 row.col f32.f16.f16.f32, accumulate in place.
__device__ __forceinline__ void mma16816(float* d, const uint32_t* a,
                                         uint32_t b0, uint32_t b1) {
    asm volatile(
        "mma.sync.aligned.m16n8k16.row.col.f32.f16.f16.f32 "
        "{%0,%1,%2,%3}, {%4,%5,%6,%7}, {%8,%9}, {%0,%1,%2,%3};"
        : "+f"(d[0]), "+f"(d[1]), "+f"(d[2]), "+f"(d[3])
        : "r"(a[0]), "r"(a[1]), "r"(a[2]), "r"(a[3]), "r"(b0), "r"(b1));
}

// MMA phase for one 8-seq group: init D with bias + fp32 x-proj, then
// accumulate W*h over K=128 (16 MMAs, 2 chains of depth 8).
#define MMA_PHASE(DG, HT, XF) do {                                             \
    _Pragma("unroll")                                                          \
    for (int e1 = 0; e1 < 2; e1++) {                                           \
        const float2 x = (XF)[e1];                                             \
        (DG)[0][e1]     = fmaf(wx1[0], x.y, fmaf(wx0[0], x.x, bsr[0]));        \
        (DG)[0][2 + e1] = fmaf(wx1[1], x.y, fmaf(wx0[1], x.x, bsr[1]));        \
        (DG)[1][e1]     = fmaf(wx1[2], x.y, fmaf(wx0[2], x.x, bsr[2]));        \
        (DG)[1][2 + e1] = fmaf(wx1[3], x.y, fmaf(wx0[3], x.x, bsr[3]));        \
    }                                                                          \
    _Pragma("unroll")                                                          \
    for (int kt = 0; kt < NKT; kt++) {                                         \
        const __half* bp = (HT) + r0 * BS + kt * 16 + c0;                      \
        const uint32_t b0 = *reinterpret_cast<const uint32_t*>(bp);            \
        const uint32_t b1 = *reinterpret_cast<const uint32_t*>(bp + 8);        \
        mma16816((DG)[0], Af[0][kt], b0, b1);                                  \
        mma16816((DG)[1], Af[1][kt], b0, b1);                                  \
    }                                                                          \
} while (0)

// Epilogue for one group: gates -> c,h update; h fp16 into the group tile;
// optionally final h fp32 to g_hid (GSEQ0 = global seq of tile row 0).
#define EPI_PHASE(DG, CC, HT, GSEQ0, LAST) do {                                \
    _Pragma("unroll")                                                          \
    for (int e1 = 0; e1 < 2; e1++) {                                           \
        const int m = c0 + e1;                                                 \
        const float gi = sigap((DG)[0][e1]);                                   \
        const float gf = sigap((DG)[0][2 + e1]);                               \
        const float gg = tanhap((DG)[1][e1]);                                  \
        const float go = sigap((DG)[1][2 + e1]);                               \
        (CC)[e1] = gf * (CC)[e1] + gi * gg;                                    \
        const float h = go * tanhap((CC)[e1]);                                 \
        (HT)[m * BS + u] = __float2half(h);                                    \
        if (LAST)                                                              \
            g_hid[(size_t)((GSEQ0) + m) * Hh + u] = h;                         \
    }                                                                          \
} while (0)

__global__ __launch_bounds__(THREADS, 1)
void lstm_hmma_kernel(const float* __restrict__ xp, const float* __restrict__ xb,
                      const float* __restrict__ p_wih, const float* __restrict__ p_whh,
                      const float* __restrict__ p_bih, const float* __restrict__ p_bhh,
                      const float* __restrict__ b_wih, const float* __restrict__ b_whh,
                      const float* __restrict__ b_bih, const float* __restrict__ b_bhh)
{
    __shared__ float2 xs[Tt * SEQS];              // [t][s]  16 KB
    __shared__ __half hA[8 * BS];                 // group A h tile (seqs 0-7)
    __shared__ __half hB[8 * BS];                 // group B h tile (seqs 8-15)

    const int tid = threadIdx.x;
    const int w   = tid >> 5;          // 0..15 -> units [8w, 8w+8)
    const int ln  = tid & 31;
    const int cta = blockIdx.x;
    const bool is_ball = (cta >= PCTAS);

    const float* wih_ = is_ball ? b_wih : p_wih;
    const float* whh_ = is_ball ? b_whh : p_whh;
    const float* bih_ = is_ball ? b_bih : p_bih;
    const float* bhh_ = is_ball ? b_bhh : p_bhh;
    const float* xsrc = is_ball ? xb : xp;
    const int s0    = is_ball ? (cta - PCTAS) * SEQS : cta * SEQS;
    const int gbase = is_ball ? NPLAYER + s0 : s0;

    // ---- zero h tiles, stage x ----
    for (int i = tid; i < 8 * BS / 2; i += THREADS) {
        reinterpret_cast<uint32_t*>(hA)[i] = 0;
        reinterpret_cast<uint32_t*>(hB)[i] = 0;
    }
    for (int i = tid; i < Tt * SEQS; i += THREADS) {
        int s = i >> 7, t = i & 127;
        xs[t * SEQS + s] = *reinterpret_cast<const float2*>(
            xsrc + (size_t)(s0 + s) * 256 + t * 2);
    }

    const int r0 = ln >> 2;            // 0..7   (gate row within 8 / B col n)
    const int c0 = (ln & 3) * 2;       // 0,2,4,6 (seq pair within group)
    const int u  = w * 8 + r0;         // hidden unit owned by this thread

    // ---- A fragments: mt0 rows = {i(u), f(u)}, mt1 rows = {g(u), o(u)} ----
    uint32_t Af[2][NKT][4];
    #pragma unroll
    for (int mt = 0; mt < 2; mt++) {
        const float* wrA = whh_ + (size_t)((mt * 2 + 0) * Hh + u) * Hh;  // i or g
        const float* wrB = whh_ + (size_t)((mt * 2 + 1) * Hh + u) * Hh;  // f or o
        #pragma unroll
        for (int kt = 0; kt < NKT; kt++) {
            const int k = kt * 16 + c0;
            float2 aA0 = *reinterpret_cast<const float2*>(wrA + k);
            float2 aB0 = *reinterpret_cast<const float2*>(wrB + k);
            float2 aA1 = *reinterpret_cast<const float2*>(wrA + k + 8);
            float2 aB1 = *reinterpret_cast<const float2*>(wrB + k + 8);
            Af[mt][kt][0] = h2pack(aA0.x, aA0.y);
            Af[mt][kt][1] = h2pack(aB0.x, aB0.y);
            Af[mt][kt][2] = h2pack(aA1.x, aA1.y);
            Af[mt][kt][3] = h2pack(aB1.x, aB1.y);
        }
    }

    // ---- per-gate x-weights and bias for unit u (i, f, g, o) ----
    float wx0[4], wx1[4], bsr[4];
    #pragma unroll
    for (int q = 0; q < 4; q++) {
        const int g = q * Hh + u;
        wx0[q] = wih_[g * 2 + 0];
        wx1[q] = wih_[g * 2 + 1];
        bsr[q] = bih_[g] + bhh_[g];
    }

    float cA[2] = {0.f, 0.f}, cB[2] = {0.f, 0.f};
    float DA[2][4], DB[2][4];
    float2 xfA[2], xfB[2];

    __syncthreads();

    // x(0) for group A
    xfA[0] = xs[0 * SEQS + c0];
    xfA[1] = xs[0 * SEQS + c0 + 1];

    // ---- pipeline prologue: t = 0 ----
    MMA_PHASE(DA, hA, xfA);
    xfB[0] = xs[0 * SEQS + 8 + c0];
    xfB[1] = xs[0 * SEQS + 8 + c0 + 1];
    __syncthreads();
    MMA_PHASE(DB, hB, xfB);
    xfA[0] = xs[1 * SEQS + c0];
    xfA[1] = xs[1 * SEQS + c0 + 1];
    EPI_PHASE(DA, cA, hA, gbase, false);
    __syncthreads();

    // ---- main pipeline: t = 1..127 ----
    #pragma unroll 1
    for (int t = 1; t < Tt; t++) {
        // phase 1: mmaA(t) || epiB(t-1)
        MMA_PHASE(DA, hA, xfA);
        xfB[0] = xs[t * SEQS + 8 + c0];
        xfB[1] = xs[t * SEQS + 8 + c0 + 1];
        EPI_PHASE(DB, cB, hB, gbase + 8, false);
        __syncthreads();
        // phase 2: mmaB(t) || epiA(t)
        MMA_PHASE(DB, hB, xfB);
        if (t + 1 < Tt) {
            xfA[0] = xs[(t + 1) * SEQS + c0];
            xfA[1] = xs[(t + 1) * SEQS + c0 + 1];
        }
        EPI_PHASE(DA, cA, hA, gbase, t == Tt - 1);
        __syncthreads();
    }

    // ---- pipeline epilogue: epiB(127) ----
    EPI_PHASE(DB, cB, hB, gbase + 8, true);
}

// FC: 128 blocks = (batch b, half of 22 players). fc_w + hidden states in smem.
#define FC_THREADS 448
__global__ __launch_bounds__(FC_THREADS)
void fc_kernel(const float* __restrict__ fc_w,
               const float* __restrict__ fc_b,
               float* __restrict__ out)
{
    __shared__ float fw[40 * 258];
    __shared__ float ph[11 * 128];
    __shared__ float ball[128];

    const int bx   = blockIdx.x;
    const int b    = bx >> 1;
    const int half = bx & 1;
    const int tid  = threadIdx.x;

    for (int idx = tid; idx < 40 * 256; idx += FC_THREADS) {
        int j = idx >> 8, k = idx & 255;
        fw[j * 258 + k] = fc_w[idx];
    }
    for (int idx = tid; idx < 11 * 128; idx += FC_THREADS) {
        int p = idx >> 7, k = idx & 127;
        ph[idx] = g_hid[(b * 22 + half * 11 + p) * Hh + k];
    }
    for (int idx = tid; idx < 128; idx += FC_THREADS)
        ball[idx] = g_hid[(NPLAYER + b) * Hh + idx];
    __syncthreads();

    if (tid < 440) {
        const int p = tid / 40;
        const int j = tid - p * 40;
        const float2* php  = (const float2*)(ph + p * 128);
        const float2* blp  = (const float2*)(ball);
        const float2* fwp0 = (const float2*)(fw + j * 258);
        const float2* fwp1 = (const float2*)(fw + j * 258 + 128);
        float acc = fc_b[j];
        #pragma unroll 8
        for (int k2 = 0; k2 < 64; k2++) {
            float2 hp = php[k2], hb = blp[k2];
            float2 w0 = fwp0[k2], w1 = fwp1[k2];
            acc += hp.x * w0.x + hp.y * w0.y + hb.x * w1.x + hb.y * w1.y;
        }
        out[(b * 22 + half * 11 + p) * 40 + j] = acc;
    }
}

extern "C" void kernel_launch(void* const* d_in, const int* in_sizes, int n_in,
                              void* d_out, int out_size)
{
    const float* xp    = (const float*)d_in[0];
    const float* xb    = (const float*)d_in[1];
    const float* p_wih = (const float*)d_in[2];
    const float* p_whh = (const float*)d_in[3];
    const float* p_bih = (const float*)d_in[4];
    const float* p_bhh = (const float*)d_in[5];
    const float* b_wih = (const float*)d_in[6];
    const float* b_whh = (const float*)d_in[7];
    const float* b_bih = (const float*)d_in[8];
    const float* b_bhh = (const float*)d_in[9];
    const float* fc_w  = (const float*)d_in[10];
    const float* fc_b  = (const float*)d_in[11];
    float* out = (float*)d_out;

    lstm_hmma_kernel<<<NCTAS, THREADS>>>(xp, xb,
                                         p_wih, p_whh, p_bih, p_bhh,
                                         b_wih, b_whh, b_bih, b_bhh);
    fc_kernel<<<128, FC_THREADS>>>(fc_w, fc_b, out);
}